// round 1
// baseline (speedup 1.0000x reference)
#include <cuda_runtime.h>
#include <math.h>

#define SEQ    4096
#define DIM    768
#define NH     12
#define HD     64
#define BATCH  2
#define MROWS  (BATCH*SEQ)    /* 8192 */
#define BHEADS (BATCH*NH)     /* 24   */

// Scratch (no cudaMalloc allowed): q,k,v in [b,h,n,d]; attn out in [b,n,dim]
__device__ float g_q[(size_t)BHEADS*SEQ*HD];
__device__ float g_k[(size_t)BHEADS*SEQ*HD];
__device__ float g_v[(size_t)BHEADS*SEQ*HD];
__device__ float g_att[(size_t)MROWS*DIM];

// ---------------------------------------------------------------------------
// QKV projection: C = X @ W^T for W in {wq,wk,wv} (blockIdx.z selects).
// 128x128 tile, 8x8 micro, K-chunk 16, smem stored K-major (transposed) so
// compute reads are float4 along M/N.  Output stored permuted [b,h,n,d].
// ---------------------------------------------------------------------------
__global__ __launch_bounds__(256, 2)
void qkv_kernel(const float* __restrict__ x,
                const float* __restrict__ wq,
                const float* __restrict__ wk,
                const float* __restrict__ wv)
{
    __shared__ float AsT[16][128];
    __shared__ float BsT[16][128];

    const float* W;
    float* out;
    if (blockIdx.z == 0)      { W = wq; out = g_q; }
    else if (blockIdx.z == 1) { W = wk; out = g_k; }
    else                      { W = wv; out = g_v; }

    const int tid  = threadIdx.x;
    const int m0   = blockIdx.x * 128;
    const int n0   = blockIdx.y * 128;
    const int lrow = tid >> 1;           // 0..127
    const int lk   = (tid & 1) * 8;      // 0 or 8
    const int ty   = tid >> 4;           // 0..15
    const int tx   = tid & 15;           // 0..15

    const float* ap = x + (size_t)(m0 + lrow) * DIM + lk;
    const float* bp = W + (size_t)(n0 + lrow) * DIM + lk;

    float acc[8][8];
#pragma unroll
    for (int i = 0; i < 8; i++)
#pragma unroll
        for (int j = 0; j < 8; j++) acc[i][j] = 0.f;

    for (int kc = 0; kc < DIM; kc += 16) {
        float4 a0 = *(const float4*)(ap + kc);
        float4 a1 = *(const float4*)(ap + kc + 4);
        float4 b0 = *(const float4*)(bp + kc);
        float4 b1 = *(const float4*)(bp + kc + 4);
        __syncthreads();   // previous chunk's compute done
        AsT[lk+0][lrow] = a0.x; AsT[lk+1][lrow] = a0.y;
        AsT[lk+2][lrow] = a0.z; AsT[lk+3][lrow] = a0.w;
        AsT[lk+4][lrow] = a1.x; AsT[lk+5][lrow] = a1.y;
        AsT[lk+6][lrow] = a1.z; AsT[lk+7][lrow] = a1.w;
        BsT[lk+0][lrow] = b0.x; BsT[lk+1][lrow] = b0.y;
        BsT[lk+2][lrow] = b0.z; BsT[lk+3][lrow] = b0.w;
        BsT[lk+4][lrow] = b1.x; BsT[lk+5][lrow] = b1.y;
        BsT[lk+6][lrow] = b1.z; BsT[lk+7][lrow] = b1.w;
        __syncthreads();
#pragma unroll
        for (int kk = 0; kk < 16; kk++) {
            float av[8], bv[8];
            *(float4*)&av[0] = *(const float4*)&AsT[kk][ty*8];
            *(float4*)&av[4] = *(const float4*)&AsT[kk][ty*8+4];
            *(float4*)&bv[0] = *(const float4*)&BsT[kk][tx*8];
            *(float4*)&bv[4] = *(const float4*)&BsT[kk][tx*8+4];
#pragma unroll
            for (int i = 0; i < 8; i++)
#pragma unroll
                for (int j = 0; j < 8; j++)
                    acc[i][j] = fmaf(av[i], bv[j], acc[i][j]);
        }
    }

    // Store permuted to [b, h, n, d]
#pragma unroll
    for (int i = 0; i < 8; i++) {
        int m = m0 + ty*8 + i;
        int b = m >> 12;            // /SEQ
        int n = m & (SEQ - 1);
#pragma unroll
        for (int jj = 0; jj < 8; jj += 4) {
            int o    = n0 + tx*8 + jj;
            int head = o >> 6;
            int dc   = o & (HD - 1);
            float4 v = make_float4(acc[i][jj], acc[i][jj+1], acc[i][jj+2], acc[i][jj+3]);
            *(float4*)(out + ((size_t)(b*NH + head)*SEQ + n)*HD + dc) = v;
        }
    }
}

// ---------------------------------------------------------------------------
// Flash attention: one block = 128 queries of one (b,h); streams 64-wide KV
// tiles with online softmax. 256 threads, 8x4 micro-tiles.
// smem: QsT[64][128] | KsT[64][64] | Vs[64][64] | Ps[128][64] = 96 KB dynamic.
// ---------------------------------------------------------------------------
__global__ __launch_bounds__(256, 2)
void attn_kernel()
{
    extern __shared__ float sm[];
    float* QsT = sm;                 // [k][r]  64*128
    float* KsT = QsT + 64*128;       // [k][c]  64*64
    float* Vs  = KsT + 64*64;        // [kv][d] 64*64
    float* Ps  = Vs  + 64*64;        // [r][kv] 128*64

    const int bh  = blockIdx.x;
    const int q0  = blockIdx.y * 128;
    const int tid = threadIdx.x;
    const int ty  = tid >> 4;        // 0..15 -> rows ty*8..+7
    const int tx  = tid & 15;        // 0..15 -> cols tx*4..+3
    const int r0  = ty * 8;

    const float scale = 0.125f;      // 64^-0.5, folded into Q load
    const float* Qg = g_q + (size_t)bh * SEQ * HD;
    const float* Kg = g_k + (size_t)bh * SEQ * HD;
    const float* Vg = g_v + (size_t)bh * SEQ * HD;

    // Load Q tile (scaled), transposed in smem
    {
        int r = tid >> 1;                 // 0..127
        int ko = (tid & 1) * 32;
        const float* qp = Qg + (size_t)(q0 + r)*HD + ko;
#pragma unroll
        for (int u = 0; u < 32; u += 4) {
            float4 v = *(const float4*)(qp + u);
            QsT[(ko+u+0)*128 + r] = v.x * scale;
            QsT[(ko+u+1)*128 + r] = v.y * scale;
            QsT[(ko+u+2)*128 + r] = v.z * scale;
            QsT[(ko+u+3)*128 + r] = v.w * scale;
        }
    }

    float m_i[8], l_i[8], acc[8][4];
#pragma unroll
    for (int i = 0; i < 8; i++) {
        m_i[i] = -INFINITY; l_i[i] = 0.f;
#pragma unroll
        for (int j = 0; j < 4; j++) acc[i][j] = 0.f;
    }

    const int rr = tid >> 2;          // 0..63
    const int ko2 = (tid & 3) * 16;   // 0,16,32,48

    for (int t = 0; t < SEQ/64; t++) {
        const int k0 = t * 64;
        const float* kp = Kg + (size_t)(k0 + rr)*HD + ko2;
        const float* vp = Vg + (size_t)(k0 + rr)*HD + ko2;
        float4 kreg[4], vreg[4];
#pragma unroll
        for (int u = 0; u < 4; u++) {
            kreg[u] = *(const float4*)(kp + u*4);
            vreg[u] = *(const float4*)(vp + u*4);
        }
        __syncthreads();   // previous tile's PV readers done with KsT/Vs/Ps
#pragma unroll
        for (int u = 0; u < 4; u++) {
            int kb = ko2 + u*4;
            KsT[(kb+0)*64 + rr] = kreg[u].x;
            KsT[(kb+1)*64 + rr] = kreg[u].y;
            KsT[(kb+2)*64 + rr] = kreg[u].z;
            KsT[(kb+3)*64 + rr] = kreg[u].w;
            *(float4*)&Vs[rr*64 + kb] = vreg[u];
        }
        __syncthreads();

        // S = Q K^T  (128x64 tile; this thread: 8 rows x 4 cols)
        float s[8][4];
#pragma unroll
        for (int i = 0; i < 8; i++)
#pragma unroll
            for (int j = 0; j < 4; j++) s[i][j] = 0.f;
#pragma unroll 8
        for (int kk = 0; kk < 64; kk++) {
            float a[8], bb[4];
            *(float4*)&a[0] = *(const float4*)&QsT[kk*128 + r0];
            *(float4*)&a[4] = *(const float4*)&QsT[kk*128 + r0 + 4];
            *(float4*)&bb[0] = *(const float4*)&KsT[kk*64 + tx*4];
#pragma unroll
            for (int i = 0; i < 8; i++)
#pragma unroll
                for (int j = 0; j < 4; j++)
                    s[i][j] = fmaf(a[i], bb[j], s[i][j]);
        }

        // Online softmax update (row stats replicated across the 16 tx lanes)
#pragma unroll
        for (int i = 0; i < 8; i++) {
            float tmax = fmaxf(fmaxf(s[i][0], s[i][1]), fmaxf(s[i][2], s[i][3]));
#pragma unroll
            for (int off = 8; off > 0; off >>= 1)
                tmax = fmaxf(tmax, __shfl_xor_sync(0xffffffffu, tmax, off));
            float mn = fmaxf(m_i[i], tmax);
            float al = __expf(m_i[i] - mn);
            float rs = 0.f;
#pragma unroll
            for (int j = 0; j < 4; j++) {
                float p = __expf(s[i][j] - mn);
                s[i][j] = p;
                rs += p;
            }
#pragma unroll
            for (int off = 8; off > 0; off >>= 1)
                rs += __shfl_xor_sync(0xffffffffu, rs, off);
            l_i[i] = l_i[i] * al + rs;
            m_i[i] = mn;
#pragma unroll
            for (int j = 0; j < 4; j++) acc[i][j] *= al;
            *(float4*)&Ps[(r0+i)*64 + tx*4] = make_float4(s[i][0], s[i][1], s[i][2], s[i][3]);
        }
        __syncthreads();

        // O += P V  (128x64 @ 64x64)
#pragma unroll 4
        for (int kv = 0; kv < 64; kv += 4) {
            float4 pv[8];
#pragma unroll
            for (int i = 0; i < 8; i++)
                pv[i] = *(const float4*)&Ps[(r0+i)*64 + kv];
#pragma unroll
            for (int u = 0; u < 4; u++) {
                float4 vb = *(const float4*)&Vs[(kv+u)*64 + tx*4];
#pragma unroll
                for (int i = 0; i < 8; i++) {
                    float p = (u == 0) ? pv[i].x : (u == 1) ? pv[i].y
                            : (u == 2) ? pv[i].z : pv[i].w;
                    acc[i][0] = fmaf(p, vb.x, acc[i][0]);
                    acc[i][1] = fmaf(p, vb.y, acc[i][1]);
                    acc[i][2] = fmaf(p, vb.z, acc[i][2]);
                    acc[i][3] = fmaf(p, vb.w, acc[i][3]);
                }
            }
        }
    }

    // Epilogue: normalize and store to [b, n, dim]
    const int b    = bh / NH;
    const int head = bh % NH;
#pragma unroll
    for (int i = 0; i < 8; i++) {
        float inv = 1.f / l_i[i];
        int n = q0 + r0 + i;
        float4 o = make_float4(acc[i][0]*inv, acc[i][1]*inv, acc[i][2]*inv, acc[i][3]*inv);
        *(float4*)(g_att + ((size_t)b*SEQ + n)*DIM + head*HD + tx*4) = o;
    }
}

// ---------------------------------------------------------------------------
// Output projection: d_out = g_att @ wo^T + bo   (same GEMM scheme)
// ---------------------------------------------------------------------------
__global__ __launch_bounds__(256, 2)
void proj_kernel(const float* __restrict__ wo,
                 const float* __restrict__ bo,
                 float* __restrict__ out)
{
    __shared__ float AsT[16][128];
    __shared__ float BsT[16][128];

    const int tid  = threadIdx.x;
    const int m0   = blockIdx.x * 128;
    const int n0   = blockIdx.y * 128;
    const int lrow = tid >> 1;
    const int lk   = (tid & 1) * 8;
    const int ty   = tid >> 4;
    const int tx   = tid & 15;

    const float* ap = g_att + (size_t)(m0 + lrow) * DIM + lk;
    const float* bp = wo    + (size_t)(n0 + lrow) * DIM + lk;

    float acc[8][8];
#pragma unroll
    for (int i = 0; i < 8; i++)
#pragma unroll
        for (int j = 0; j < 8; j++) acc[i][j] = 0.f;

    for (int kc = 0; kc < DIM; kc += 16) {
        float4 a0 = *(const float4*)(ap + kc);
        float4 a1 = *(const float4*)(ap + kc + 4);
        float4 b0 = *(const float4*)(bp + kc);
        float4 b1 = *(const float4*)(bp + kc + 4);
        __syncthreads();
        AsT[lk+0][lrow] = a0.x; AsT[lk+1][lrow] = a0.y;
        AsT[lk+2][lrow] = a0.z; AsT[lk+3][lrow] = a0.w;
        AsT[lk+4][lrow] = a1.x; AsT[lk+5][lrow] = a1.y;
        AsT[lk+6][lrow] = a1.z; AsT[lk+7][lrow] = a1.w;
        BsT[lk+0][lrow] = b0.x; BsT[lk+1][lrow] = b0.y;
        BsT[lk+2][lrow] = b0.z; BsT[lk+3][lrow] = b0.w;
        BsT[lk+4][lrow] = b1.x; BsT[lk+5][lrow] = b1.y;
        BsT[lk+6][lrow] = b1.z; BsT[lk+7][lrow] = b1.w;
        __syncthreads();
#pragma unroll
        for (int kk = 0; kk < 16; kk++) {
            float av[8], bv[8];
            *(float4*)&av[0] = *(const float4*)&AsT[kk][ty*8];
            *(float4*)&av[4] = *(const float4*)&AsT[kk][ty*8+4];
            *(float4*)&bv[0] = *(const float4*)&BsT[kk][tx*8];
            *(float4*)&bv[4] = *(const float4*)&BsT[kk][tx*8+4];
#pragma unroll
            for (int i = 0; i < 8; i++)
#pragma unroll
                for (int j = 0; j < 8; j++)
                    acc[i][j] = fmaf(av[i], bv[j], acc[i][j]);
        }
    }

#pragma unroll
    for (int i = 0; i < 8; i++) {
        int m = m0 + ty*8 + i;
#pragma unroll
        for (int jj = 0; jj < 8; jj += 4) {
            int o = n0 + tx*8 + jj;
            float4 bb = *(const float4*)(bo + o);
            float4 v = make_float4(acc[i][jj]   + bb.x,
                                   acc[i][jj+1] + bb.y,
                                   acc[i][jj+2] + bb.z,
                                   acc[i][jj+3] + bb.w);
            *(float4*)(out + (size_t)m*DIM + o) = v;
        }
    }
}

// ---------------------------------------------------------------------------
extern "C" void kernel_launch(void* const* d_in, const int* in_sizes, int n_in,
                              void* d_out, int out_size)
{
    const float* x  = (const float*)d_in[0];
    const float* wq = (const float*)d_in[1];
    const float* wk = (const float*)d_in[2];
    const float* wv = (const float*)d_in[3];
    const float* wo = (const float*)d_in[4];
    const float* bo = (const float*)d_in[5];
    float* out = (float*)d_out;

    (void)in_sizes; (void)n_in; (void)out_size;

    cudaFuncSetAttribute(attn_kernel,
                         cudaFuncAttributeMaxDynamicSharedMemorySize, 96*1024);

    qkv_kernel<<<dim3(MROWS/128, DIM/128, 3), 256>>>(x, wq, wk, wv);
    attn_kernel<<<dim3(BHEADS, SEQ/128), 256, 96*1024>>>();
    proj_kernel<<<dim3(MROWS/128, DIM/128), 256>>>(wo, bo, out);
}